// round 1
// baseline (speedup 1.0000x reference)
#include <cuda_runtime.h>
#include <math.h>

#define T_SEQ 4096
#define DIM 1024
#define HEADS 16
#define KV_HEADS 4
#define HD 64
#define KV_DIM 256
#define SCALE_F 0.125f   // 64^-0.5

// Scratch (allocation-free rule: __device__ globals)
__device__ float g_Q[T_SEQ * DIM];     // Q projection, [t][h*64+d]
__device__ float g_att[T_SEQ * DIM];   // attention output, [t][h*64+d]

// ---------------------------------------------------------------------------
// GEMM: C = A[M,Kd] @ W[N,Kd]^T + bias[N]
// kv_scatter=0: C[m*N+n]
// kv_scatter=1: C[(n/64)*T*64 + m*64 + (n%64)]  (kv-cache [Hk,T,hd] layout)
// ---------------------------------------------------------------------------
__global__ void gemm_bias(const float* __restrict__ A,
                          const float* __restrict__ W,
                          const float* __restrict__ bias,
                          float* __restrict__ C,
                          int M, int N, int Kd, int kv_scatter)
{
    __shared__ float As[64][65];
    __shared__ float Ws[64][65];

    int tid = threadIdx.x;
    int tx = tid & 15, ty = tid >> 4;
    int nb = blockIdx.x * 64;
    int mb = blockIdx.y * 64;

    float acc[4][4];
    #pragma unroll
    for (int i = 0; i < 4; i++)
        #pragma unroll
        for (int j = 0; j < 4; j++) acc[i][j] = 0.f;

    for (int k0 = 0; k0 < Kd; k0 += 64) {
        #pragma unroll
        for (int idx = tid; idx < 64 * 64; idx += 256) {
            int r = idx >> 6, c = idx & 63;
            As[r][c] = A[(size_t)(mb + r) * Kd + k0 + c];
            Ws[r][c] = W[(size_t)(nb + r) * Kd + k0 + c];
        }
        __syncthreads();

        #pragma unroll 16
        for (int kk = 0; kk < 64; kk++) {
            float a[4], w[4];
            #pragma unroll
            for (int i = 0; i < 4; i++) a[i] = As[ty * 4 + i][kk];
            #pragma unroll
            for (int j = 0; j < 4; j++) w[j] = Ws[tx * 4 + j][kk];
            #pragma unroll
            for (int i = 0; i < 4; i++)
                #pragma unroll
                for (int j = 0; j < 4; j++)
                    acc[i][j] = fmaf(a[i], w[j], acc[i][j]);
        }
        __syncthreads();
    }

    #pragma unroll
    for (int i = 0; i < 4; i++) {
        int mm = mb + ty * 4 + i;
        #pragma unroll
        for (int j = 0; j < 4; j++) {
            int nn = nb + tx * 4 + j;
            float v = acc[i][j] + bias[nn];
            if (kv_scatter)
                C[(size_t)(nn >> 6) * (T_SEQ * HD) + (size_t)mm * HD + (nn & 63)] = v;
            else
                C[(size_t)mm * N + nn] = v;
        }
    }
}

// ---------------------------------------------------------------------------
// Causal flash attention. One CTA = 64 query rows of one head.
// Q: [t][h*64+d], Kc/Vc: [Hk][t][64], O: [t][h*64+d]
// ---------------------------------------------------------------------------
__global__ void flash_attn(const float* __restrict__ Q,
                           const float* __restrict__ Kc,
                           const float* __restrict__ Vc,
                           float* __restrict__ O)
{
    __shared__ float Qs[64][65];
    __shared__ float Ks[32][65];
    __shared__ float Vs[32][65];
    __shared__ float Ps[64][33];

    int tid = threadIdx.x;
    int tx = tid & 15, ty = tid >> 4;
    int qb = blockIdx.x, h = blockIdx.y;
    int kvh = h >> 2;
    int qstart = qb * 64;
    const float* Kh = Kc + (size_t)kvh * T_SEQ * HD;
    const float* Vh = Vc + (size_t)kvh * T_SEQ * HD;

    // Load Q tile (rows qstart..qstart+63, head h)
    #pragma unroll
    for (int idx = tid; idx < 64 * 64; idx += 256) {
        int r = idx >> 6, d = idx & 63;
        Qs[r][d] = Q[(size_t)(qstart + r) * DIM + h * HD + d];
    }

    float acc[4][4];
    float m[4], l[4];
    #pragma unroll
    for (int i = 0; i < 4; i++) {
        m[i] = -1e30f; l[i] = 0.f;
        #pragma unroll
        for (int j = 0; j < 4; j++) acc[i][j] = 0.f;
    }

    int nkb = 2 * qb + 2;  // key blocks of 32 needed for causal coverage
    for (int kb = 0; kb < nkb; kb++) {
        int kstart = kb * 32;
        __syncthreads();  // protect Ks/Vs/Ps from previous iteration reads
        #pragma unroll
        for (int idx = tid; idx < 32 * 64; idx += 256) {
            int r = idx >> 6, d = idx & 63;
            Ks[r][d] = Kh[(size_t)(kstart + r) * HD + d];
            Vs[r][d] = Vh[(size_t)(kstart + r) * HD + d];
        }
        __syncthreads();

        // S = Q @ K^T for this tile: each thread 4 rows x 2 cols
        float s[4][2];
        #pragma unroll
        for (int i = 0; i < 4; i++) { s[i][0] = 0.f; s[i][1] = 0.f; }

        #pragma unroll 16
        for (int d = 0; d < 64; d++) {
            float qv[4], kv[2];
            #pragma unroll
            for (int i = 0; i < 4; i++) qv[i] = Qs[ty * 4 + i][d];
            kv[0] = Ks[tx * 2 + 0][d];
            kv[1] = Ks[tx * 2 + 1][d];
            #pragma unroll
            for (int i = 0; i < 4; i++) {
                s[i][0] = fmaf(qv[i], kv[0], s[i][0]);
                s[i][1] = fmaf(qv[i], kv[1], s[i][1]);
            }
        }

        // scale + causal mask
        #pragma unroll
        for (int i = 0; i < 4; i++) {
            int gr = qstart + ty * 4 + i;
            #pragma unroll
            for (int j = 0; j < 2; j++) {
                int gc = kstart + tx * 2 + j;
                s[i][j] = (gc <= gr) ? s[i][j] * SCALE_F : -1e30f;
            }
        }

        // online softmax (row reduce across 16 lanes)
        #pragma unroll
        for (int i = 0; i < 4; i++) {
            float mx = fmaxf(s[i][0], s[i][1]);
            #pragma unroll
            for (int o = 8; o >= 1; o >>= 1)
                mx = fmaxf(mx, __shfl_xor_sync(0xffffffffu, mx, o));
            float nm = fmaxf(m[i], mx);
            float p0 = __expf(s[i][0] - nm);
            float p1 = __expf(s[i][1] - nm);
            float rs = p0 + p1;
            #pragma unroll
            for (int o = 8; o >= 1; o >>= 1)
                rs += __shfl_xor_sync(0xffffffffu, rs, o);
            float alpha = __expf(m[i] - nm);
            l[i] = l[i] * alpha + rs;
            m[i] = nm;
            #pragma unroll
            for (int j = 0; j < 4; j++) acc[i][j] *= alpha;
            Ps[ty * 4 + i][tx * 2 + 0] = p0;
            Ps[ty * 4 + i][tx * 2 + 1] = p1;
        }
        __syncthreads();

        // O += P @ V
        #pragma unroll 8
        for (int c = 0; c < 32; c++) {
            float vv[4], pv[4];
            #pragma unroll
            for (int j = 0; j < 4; j++) vv[j] = Vs[c][tx * 4 + j];
            #pragma unroll
            for (int i = 0; i < 4; i++) pv[i] = Ps[ty * 4 + i][c];
            #pragma unroll
            for (int i = 0; i < 4; i++)
                #pragma unroll
                for (int j = 0; j < 4; j++)
                    acc[i][j] = fmaf(pv[i], vv[j], acc[i][j]);
        }
    }

    // epilogue: normalize and store [t][h*64+d]
    #pragma unroll
    for (int i = 0; i < 4; i++) {
        float inv = 1.f / l[i];
        int gr = qstart + ty * 4 + i;
        #pragma unroll
        for (int j = 0; j < 4; j++)
            O[(size_t)gr * DIM + h * HD + tx * 4 + j] = acc[i][j] * inv;
    }
}

// ---------------------------------------------------------------------------
extern "C" void kernel_launch(void* const* d_in, const int* in_sizes, int n_in,
                              void* d_out, int out_size)
{
    const float* x   = (const float*)d_in[0];
    // d_in[1] = mask (causal tril) — implemented analytically
    const float* q_w = (const float*)d_in[2];
    const float* q_b = (const float*)d_in[3];
    const float* k_w = (const float*)d_in[4];
    const float* k_b = (const float*)d_in[5];
    const float* v_w = (const float*)d_in[6];
    const float* v_b = (const float*)d_in[7];
    const float* o_w = (const float*)d_in[8];
    const float* o_b = (const float*)d_in[9];

    float* out  = (float*)d_out;                         // [T, DIM]
    float* kout = out + (size_t)T_SEQ * DIM;             // [Hk, T, 64]
    float* vout = kout + (size_t)KV_HEADS * T_SEQ * HD;  // [Hk, T, 64]

    float* qbuf = nullptr;
    float* abuf = nullptr;
    cudaGetSymbolAddress((void**)&qbuf, g_Q);
    cudaGetSymbolAddress((void**)&abuf, g_att);

    // Q projection -> g_Q  [t][h*64+d]
    gemm_bias<<<dim3(DIM / 64, T_SEQ / 64), 256>>>(x, q_w, q_b, qbuf,
                                                   T_SEQ, DIM, DIM, 0);
    // K projection -> kout (kv layout)
    gemm_bias<<<dim3(KV_DIM / 64, T_SEQ / 64), 256>>>(x, k_w, k_b, kout,
                                                      T_SEQ, KV_DIM, DIM, 1);
    // V projection -> vout (kv layout)
    gemm_bias<<<dim3(KV_DIM / 64, T_SEQ / 64), 256>>>(x, v_w, v_b, vout,
                                                      T_SEQ, KV_DIM, DIM, 1);
    // causal attention -> g_att
    flash_attn<<<dim3(T_SEQ / 64, HEADS), 256>>>(qbuf, kout, vout, abuf);
    // output projection -> out
    gemm_bias<<<dim3(DIM / 64, T_SEQ / 64), 256>>>(abuf, o_w, o_b, out,
                                                   T_SEQ, DIM, DIM, 0);
}

// round 2
// speedup vs baseline: 2.4168x; 2.4168x over previous
#include <cuda_runtime.h>
#include <math.h>

#define T_SEQ 4096
#define DIM 1024
#define HEADS 16
#define KV_HEADS 4
#define HD 64
#define KV_DIM 256
#define SCALE_F 0.125f   // 64^-0.5

__device__ float g_Q[T_SEQ * DIM];     // Q projection, [t][h*64+d]
__device__ float g_att[T_SEQ * DIM];   // attention output, [t][h*64+d]

__device__ __forceinline__ unsigned f2tf(float x) {
    unsigned r;
    asm("cvt.rna.tf32.f32 %0, %1;" : "=r"(r) : "f"(x));
    return r;
}

__device__ __forceinline__ void mma_tf32(float* c, const unsigned* a, const unsigned* b) {
    asm volatile(
        "mma.sync.aligned.m16n8k8.row.col.f32.tf32.tf32.f32 "
        "{%0,%1,%2,%3}, {%4,%5,%6,%7}, {%8,%9}, {%0,%1,%2,%3};\n"
        : "+f"(c[0]), "+f"(c[1]), "+f"(c[2]), "+f"(c[3])
        : "r"(a[0]), "r"(a[1]), "r"(a[2]), "r"(a[3]),
          "r"(b[0]), "r"(b[1]));
}

// ---------------------------------------------------------------------------
// TF32 GEMM: C = A[M,Kd] @ W[N,Kd]^T + bias[N]
// ---------------------------------------------------------------------------
__global__ void gemm_tf32(const float* __restrict__ A,
                          const float* __restrict__ W,
                          const float* __restrict__ bias,
                          float* __restrict__ C,
                          int M, int N, int Kd, int kv_scatter)
{
    __shared__ unsigned As[128][36];
    __shared__ unsigned Ws2[128][36];

    int tid  = threadIdx.x;
    int lane = tid & 31;
    int warp = tid >> 5;
    int wm = warp & 1;
    int wn = warp >> 1;
    int nb = blockIdx.x * 128;
    int mb = blockIdx.y * 128;

    float acc[4][4][4];
    #pragma unroll
    for (int mt = 0; mt < 4; mt++)
        #pragma unroll
        for (int nt = 0; nt < 4; nt++)
            #pragma unroll
            for (int i = 0; i < 4; i++) acc[mt][nt][i] = 0.f;

    int lr = tid >> 3;
    int lc = (tid & 7) * 4;

    for (int k0 = 0; k0 < Kd; k0 += 32) {
        __syncthreads();
        #pragma unroll
        for (int p = 0; p < 4; p++) {
            int row = lr + 32 * p;
            float4 va = *(const float4*)&A[(size_t)(mb + row) * Kd + k0 + lc];
            float4 vw = *(const float4*)&W[(size_t)(nb + row) * Kd + k0 + lc];
            As[row][lc + 0] = f2tf(va.x);
            As[row][lc + 1] = f2tf(va.y);
            As[row][lc + 2] = f2tf(va.z);
            As[row][lc + 3] = f2tf(va.w);
            Ws2[row][lc + 0] = f2tf(vw.x);
            Ws2[row][lc + 1] = f2tf(vw.y);
            Ws2[row][lc + 2] = f2tf(vw.z);
            Ws2[row][lc + 3] = f2tf(vw.w);
        }
        __syncthreads();

        #pragma unroll
        for (int kt = 0; kt < 4; kt++) {
            unsigned a[4][4], b[4][2];
            #pragma unroll
            for (int mt = 0; mt < 4; mt++) {
                int row = wm * 64 + mt * 16 + (lane >> 2);
                int col = kt * 8 + (lane & 3);
                a[mt][0] = As[row][col];
                a[mt][1] = As[row + 8][col];
                a[mt][2] = As[row][col + 4];
                a[mt][3] = As[row + 8][col + 4];
            }
            #pragma unroll
            for (int nt = 0; nt < 4; nt++) {
                int bn = wn * 32 + nt * 8 + (lane >> 2);
                int bk = kt * 8 + (lane & 3);
                b[nt][0] = Ws2[bn][bk];
                b[nt][1] = Ws2[bn][bk + 4];
            }
            #pragma unroll
            for (int mt = 0; mt < 4; mt++)
                #pragma unroll
                for (int nt = 0; nt < 4; nt++)
                    mma_tf32(acc[mt][nt], a[mt], b[nt]);
        }
    }

    #pragma unroll
    for (int mt = 0; mt < 4; mt++) {
        int mm = mb + wm * 64 + mt * 16 + (lane >> 2);
        #pragma unroll
        for (int nt = 0; nt < 4; nt++) {
            int nn = nb + wn * 32 + nt * 8 + 2 * (lane & 3);
            float b0 = bias[nn], b1 = bias[nn + 1];
            float2 v0 = make_float2(acc[mt][nt][0] + b0, acc[mt][nt][1] + b1);
            float2 v1 = make_float2(acc[mt][nt][2] + b0, acc[mt][nt][3] + b1);
            if (kv_scatter) {
                size_t base = (size_t)(nn >> 6) * (T_SEQ * HD) + (nn & 63);
                *(float2*)&C[base + (size_t)mm * HD] = v0;
                *(float2*)&C[base + (size_t)(mm + 8) * HD] = v1;
            } else {
                *(float2*)&C[(size_t)mm * N + nn] = v0;
                *(float2*)&C[(size_t)(mm + 8) * N + nn] = v1;
            }
        }
    }
}

// ---------------------------------------------------------------------------
// TF32 flash attention (causal). CTA = 64 q-rows x one head, 4 warps.
// ---------------------------------------------------------------------------
struct FlashSmem {
    unsigned Qs[64][68];
    unsigned Ks[64][68];
    unsigned Vs[64][72];
    unsigned Ps[4][16][68];
};

__global__ void flash_tf32(const float* __restrict__ Q,
                           const float* __restrict__ Kc,
                           const float* __restrict__ Vc,
                           float* __restrict__ O)
{
    extern __shared__ FlashSmem sm[];
    FlashSmem& s = sm[0];

    int tid = threadIdx.x;
    int lane = tid & 31;
    int w = tid >> 5;
    int qb = blockIdx.x;
    int h = blockIdx.y;
    int kvh = h >> 2;
    int qstart = qb * 64;
    const float* Kh = Kc + (size_t)kvh * T_SEQ * HD;
    const float* Vh = Vc + (size_t)kvh * T_SEQ * HD;

    // load Q tile (apply softmax scale here; exact power of two)
    {
        int r = tid >> 1;
        #pragma unroll
        for (int i = 0; i < 8; i++) {
            int c = ((tid & 1) * 8 + i) * 4;
            float4 v = *(const float4*)&Q[(size_t)(qstart + r) * DIM + h * HD + c];
            s.Qs[r][c + 0] = f2tf(v.x * SCALE_F);
            s.Qs[r][c + 1] = f2tf(v.y * SCALE_F);
            s.Qs[r][c + 2] = f2tf(v.z * SCALE_F);
            s.Qs[r][c + 3] = f2tf(v.w * SCALE_F);
        }
    }
    __syncthreads();

    unsigned qf[8][4];
    {
        int row = w * 16 + (lane >> 2);
        #pragma unroll
        for (int kt = 0; kt < 8; kt++) {
            int col = kt * 8 + (lane & 3);
            qf[kt][0] = s.Qs[row][col];
            qf[kt][1] = s.Qs[row + 8][col];
            qf[kt][2] = s.Qs[row][col + 4];
            qf[kt][3] = s.Qs[row + 8][col + 4];
        }
    }

    float oacc[8][4];
    #pragma unroll
    for (int nt = 0; nt < 8; nt++)
        #pragma unroll
        for (int i = 0; i < 4; i++) oacc[nt][i] = 0.f;
    float m0 = -1e30f, m1 = -1e30f, l0 = 0.f, l1 = 0.f;

    int r0g = qstart + w * 16 + (lane >> 2);
    int r1g = r0g + 8;

    for (int kb = 0; kb <= qb; kb++) {
        int kstart = kb * 64;

        __syncthreads();
        {
            int r = tid >> 1;
            #pragma unroll
            for (int i = 0; i < 8; i++) {
                int c = ((tid & 1) * 8 + i) * 4;
                float4 vk = *(const float4*)&Kh[(size_t)(kstart + r) * HD + c];
                float4 vv = *(const float4*)&Vh[(size_t)(kstart + r) * HD + c];
                s.Ks[r][c + 0] = f2tf(vk.x);
                s.Ks[r][c + 1] = f2tf(vk.y);
                s.Ks[r][c + 2] = f2tf(vk.z);
                s.Ks[r][c + 3] = f2tf(vk.w);
                s.Vs[r][c + 0] = f2tf(vv.x);
                s.Vs[r][c + 1] = f2tf(vv.y);
                s.Vs[r][c + 2] = f2tf(vv.z);
                s.Vs[r][c + 3] = f2tf(vv.w);
            }
        }
        __syncthreads();

        float sacc[8][4];
        #pragma unroll
        for (int nt = 0; nt < 8; nt++)
            #pragma unroll
            for (int i = 0; i < 4; i++) sacc[nt][i] = 0.f;

        #pragma unroll
        for (int kt = 0; kt < 8; kt++) {
            #pragma unroll
            for (int nt = 0; nt < 8; nt++) {
                unsigned b[2];
                int bn = nt * 8 + (lane >> 2);
                int bk = kt * 8 + (lane & 3);
                b[0] = s.Ks[bn][bk];
                b[1] = s.Ks[bn][bk + 4];
                mma_tf32(sacc[nt], qf[kt], b);
            }
        }

        if (kb == qb) {
            #pragma unroll
            for (int nt = 0; nt < 8; nt++) {
                int c0 = kstart + nt * 8 + 2 * (lane & 3);
                int c1 = c0 + 1;
                if (c0 > r0g) sacc[nt][0] = -1e30f;
                if (c1 > r0g) sacc[nt][1] = -1e30f;
                if (c0 > r1g) sacc[nt][2] = -1e30f;
                if (c1 > r1g) sacc[nt][3] = -1e30f;
            }
        }

        float mx0 = -1e30f, mx1 = -1e30f;
        #pragma unroll
        for (int nt = 0; nt < 8; nt++) {
            mx0 = fmaxf(mx0, fmaxf(sacc[nt][0], sacc[nt][1]));
            mx1 = fmaxf(mx1, fmaxf(sacc[nt][2], sacc[nt][3]));
        }
        mx0 = fmaxf(mx0, __shfl_xor_sync(0xffffffffu, mx0, 1));
        mx0 = fmaxf(mx0, __shfl_xor_sync(0xffffffffu, mx0, 2));
        mx1 = fmaxf(mx1, __shfl_xor_sync(0xffffffffu, mx1, 1));
        mx1 = fmaxf(mx1, __shfl_xor_sync(0xffffffffu, mx1, 2));

        float nm0 = fmaxf(m0, mx0), nm1 = fmaxf(m1, mx1);
        float alpha0 = __expf(m0 - nm0), alpha1 = __expf(m1 - nm1);
        m0 = nm0; m1 = nm1;

        __syncwarp();
        float rs0 = 0.f, rs1 = 0.f;
        {
            int pr = lane >> 2;
            int pc = 2 * (lane & 3);
            #pragma unroll
            for (int nt = 0; nt < 8; nt++) {
                float p00 = __expf(sacc[nt][0] - nm0);
                float p01 = __expf(sacc[nt][1] - nm0);
                float p10 = __expf(sacc[nt][2] - nm1);
                float p11 = __expf(sacc[nt][3] - nm1);
                rs0 += p00 + p01;
                rs1 += p10 + p11;
                s.Ps[w][pr][nt * 8 + pc]         = f2tf(p00);
                s.Ps[w][pr][nt * 8 + pc + 1]     = f2tf(p01);
                s.Ps[w][pr + 8][nt * 8 + pc]     = f2tf(p10);
                s.Ps[w][pr + 8][nt * 8 + pc + 1] = f2tf(p11);
            }
        }
        rs0 += __shfl_xor_sync(0xffffffffu, rs0, 1);
        rs0 += __shfl_xor_sync(0xffffffffu, rs0, 2);
        rs1 += __shfl_xor_sync(0xffffffffu, rs1, 1);
        rs1 += __shfl_xor_sync(0xffffffffu, rs1, 2);
        l0 = l0 * alpha0 + rs0;
        l1 = l1 * alpha1 + rs1;

        #pragma unroll
        for (int nt = 0; nt < 8; nt++) {
            oacc[nt][0] *= alpha0;
            oacc[nt][1] *= alpha0;
            oacc[nt][2] *= alpha1;
            oacc[nt][3] *= alpha1;
        }
        __syncwarp();

        #pragma unroll
        for (int kt = 0; kt < 8; kt++) {
            unsigned a[4];
            int ar = lane >> 2;
            int ac = kt * 8 + (lane & 3);
            a[0] = s.Ps[w][ar][ac];
            a[1] = s.Ps[w][ar + 8][ac];
            a[2] = s.Ps[w][ar][ac + 4];
            a[3] = s.Ps[w][ar + 8][ac + 4];
            #pragma unroll
            for (int nt = 0; nt < 8; nt++) {
                unsigned b[2];
                int bk = kt * 8 + (lane & 3);
                int bn = nt * 8 + (lane >> 2);
                b[0] = s.Vs[bk][bn];
                b[1] = s.Vs[bk + 4][bn];
                mma_tf32(oacc[nt], a, b);
            }
        }
    }

    float inv0 = 1.f / l0, inv1 = 1.f / l1;
    #pragma unroll
    for (int nt = 0; nt < 8; nt++) {
        int col = h * HD + nt * 8 + 2 * (lane & 3);
        float2 v0 = make_float2(oacc[nt][0] * inv0, oacc[nt][1] * inv0);
        float2 v1 = make_float2(oacc[nt][2] * inv1, oacc[nt][3] * inv1);
        *(float2*)&O[(size_t)r0g * DIM + col] = v0;
        *(float2*)&O[(size_t)r1g * DIM + col] = v1;
    }
}

// ---------------------------------------------------------------------------
extern "C" void kernel_launch(void* const* d_in, const int* in_sizes, int n_in,
                              void* d_out, int out_size)
{
    const float* x   = (const float*)d_in[0];
    const float* q_w = (const float*)d_in[2];
    const float* q_b = (const float*)d_in[3];
    const float* k_w = (const float*)d_in[4];
    const float* k_b = (const float*)d_in[5];
    const float* v_w = (const float*)d_in[6];
    const float* v_b = (const float*)d_in[7];
    const float* o_w = (const float*)d_in[8];
    const float* o_b = (const float*)d_in[9];

    float* out  = (float*)d_out;
    float* kout = out + (size_t)T_SEQ * DIM;
    float* vout = kout + (size_t)KV_HEADS * T_SEQ * HD;

    float* qbuf = nullptr;
    float* abuf = nullptr;
    cudaGetSymbolAddress((void**)&qbuf, g_Q);
    cudaGetSymbolAddress((void**)&abuf, g_att);

    cudaFuncSetAttribute(flash_tf32, cudaFuncAttributeMaxDynamicSharedMemorySize,
                         (int)sizeof(FlashSmem));

    gemm_tf32<<<dim3(DIM / 128, T_SEQ / 128), 256>>>(x, q_w, q_b, qbuf,
                                                     T_SEQ, DIM, DIM, 0);
    gemm_tf32<<<dim3(KV_DIM / 128, T_SEQ / 128), 256>>>(x, k_w, k_b, kout,
                                                        T_SEQ, KV_DIM, DIM, 1);
    gemm_tf32<<<dim3(KV_DIM / 128, T_SEQ / 128), 256>>>(x, v_w, v_b, vout,
                                                        T_SEQ, KV_DIM, DIM, 1);
    flash_tf32<<<dim3(T_SEQ / 64, HEADS), 128, sizeof(FlashSmem)>>>(qbuf, kout,
                                                                    vout, abuf);
    gemm_tf32<<<dim3(DIM / 128, T_SEQ / 128), 256>>>(abuf, o_w, o_b, out,
                                                     T_SEQ, DIM, DIM, 0);
}

// round 3
// speedup vs baseline: 3.1218x; 1.2917x over previous
#include <cuda_runtime.h>
#include <math.h>

#define T_SEQ 4096
#define DIM 1024
#define HEADS 16
#define KV_HEADS 4
#define HD 64
#define KV_DIM 256
#define SCALE_F 0.125f   // 64^-0.5

// Scratch (allocation-free rule: __device__ globals)
__device__ float g_Qt[T_SEQ * DIM];                 // tf32 Q*scale, paired cols
__device__ float g_att[T_SEQ * DIM];                // attention output (f32)
__device__ float g_Kt[KV_HEADS * T_SEQ * HD];       // tf32 K, [kvh][t][d-paired]
__device__ float g_Vt[KV_HEADS * T_SEQ * HD];       // tf32 V, [kvh][d][t-paired]

__device__ __forceinline__ unsigned f2tf(float x) {
    unsigned r;
    asm("cvt.rna.tf32.f32 %0, %1;" : "=r"(r) : "f"(x));
    return r;
}
__device__ __forceinline__ float f2tf_f(float x) {
    return __uint_as_float(f2tf(x));
}

__device__ __forceinline__ void mma_tf32(float* c, const unsigned* a, const unsigned* b) {
    asm volatile(
        "mma.sync.aligned.m16n8k8.row.col.f32.tf32.tf32.f32 "
        "{%0,%1,%2,%3}, {%4,%5,%6,%7}, {%8,%9}, {%0,%1,%2,%3};\n"
        : "+f"(c[0]), "+f"(c[1]), "+f"(c[2]), "+f"(c[3])
        : "r"(a[0]), "r"(a[1]), "r"(a[2]), "r"(a[3]),
          "r"(b[0]), "r"(b[1]));
}

// pairing permutation within an 8-column group: logical j -> phys
__device__ __host__ __forceinline__ int perm8(int j) {
    return ((j & 3) << 1) | (j >> 2);
}
__device__ __forceinline__ int colphys(int c) {
    return (c & ~7) | perm8(c & 7);
}

#define CP16(d, s) asm volatile("cp.async.cg.shared.global [%0], [%1], 16;" :: "r"(d), "l"(s))
#define CP_COMMIT() asm volatile("cp.async.commit_group;" ::: "memory")
#define CP_WAIT0() asm volatile("cp.async.wait_group 0;" ::: "memory")
#define CP_WAIT1() asm volatile("cp.async.wait_group 1;" ::: "memory")

// ---------------------------------------------------------------------------
// TF32 GEMM: C = A[M,Kd] @ W[N,Kd]^T + bias[N]
// mode 0: plain f32 store to C
// mode 1: Q-mode: store tf32(val*SCALE) to C at paired cols ([t][DIM] layout)
// mode 2: K-mode: f32 kv-cache store to C + tf32 paired copy to aux [kvh][t][d]
// mode 3: V-mode: f32 kv-cache store to C + tf32 transposed paired copy to aux [kvh][d][t]
// ---------------------------------------------------------------------------
__global__ __launch_bounds__(256, 2)
void gemm_tf32(const float* __restrict__ A,
               const float* __restrict__ W,
               const float* __restrict__ bias,
               float* __restrict__ C,
               float* __restrict__ aux,
               int M, int N, int Kd, int mode)
{
    __shared__ unsigned As[128][40];
    __shared__ unsigned Ws[128][40];

    int tid  = threadIdx.x;
    int lane = tid & 31;
    int warp = tid >> 5;
    int wm = warp & 1;
    int wn = warp >> 1;
    int nb = blockIdx.x * 128;
    int mb = blockIdx.y * 128;
    int t = lane & 3;
    int g = lane >> 2;

    float acc[4][4][4];
    #pragma unroll
    for (int mt = 0; mt < 4; mt++)
        #pragma unroll
        for (int nt = 0; nt < 4; nt++)
            #pragma unroll
            for (int i = 0; i < 4; i++) acc[mt][nt][i] = 0.f;

    int frow = tid >> 2;          // 0..63
    int fgrp = tid & 3;           // col group of 8

    for (int k0 = 0; k0 < Kd; k0 += 32) {
        __syncthreads();
        #pragma unroll
        for (int p = 0; p < 2; p++) {
            int row = frow + 64 * p;
            const float* pa = &A[(size_t)(mb + row) * Kd + k0 + fgrp * 8];
            const float* pw = &W[(size_t)(nb + row) * Kd + k0 + fgrp * 8];
            float4 alo = *(const float4*)pa;
            float4 ahi = *(const float4*)(pa + 4);
            float4 wlo = *(const float4*)pw;
            float4 whi = *(const float4*)(pw + 4);
            uint4 a0 = make_uint4(f2tf(alo.x), f2tf(ahi.x), f2tf(alo.y), f2tf(ahi.y));
            uint4 a1 = make_uint4(f2tf(alo.z), f2tf(ahi.z), f2tf(alo.w), f2tf(ahi.w));
            uint4 w0 = make_uint4(f2tf(wlo.x), f2tf(whi.x), f2tf(wlo.y), f2tf(whi.y));
            uint4 w1 = make_uint4(f2tf(wlo.z), f2tf(whi.z), f2tf(wlo.w), f2tf(whi.w));
            *(uint4*)&As[row][fgrp * 8]     = a0;
            *(uint4*)&As[row][fgrp * 8 + 4] = a1;
            *(uint4*)&Ws[row][fgrp * 8]     = w0;
            *(uint4*)&Ws[row][fgrp * 8 + 4] = w1;
        }
        __syncthreads();

        #pragma unroll
        for (int kt = 0; kt < 4; kt++) {
            unsigned a[4][4], b[4][2];
            #pragma unroll
            for (int mt = 0; mt < 4; mt++) {
                int row = wm * 64 + mt * 16 + g;
                uint2 v0 = *(uint2*)&As[row][kt * 8 + 2 * t];
                uint2 v1 = *(uint2*)&As[row + 8][kt * 8 + 2 * t];
                a[mt][0] = v0.x; a[mt][1] = v1.x; a[mt][2] = v0.y; a[mt][3] = v1.y;
            }
            #pragma unroll
            for (int nt = 0; nt < 4; nt++) {
                int bn = wn * 32 + nt * 8 + g;
                uint2 vb = *(uint2*)&Ws[bn][kt * 8 + 2 * t];
                b[nt][0] = vb.x; b[nt][1] = vb.y;
            }
            #pragma unroll
            for (int mt = 0; mt < 4; mt++)
                #pragma unroll
                for (int nt = 0; nt < 4; nt++)
                    mma_tf32(acc[mt][nt], a[mt], b[nt]);
        }
    }

    #pragma unroll
    for (int mt = 0; mt < 4; mt++) {
        int mm = mb + wm * 64 + mt * 16 + g;
        #pragma unroll
        for (int nt = 0; nt < 4; nt++) {
            int nn = nb + wn * 32 + nt * 8 + 2 * t;
            float b0 = bias[nn], b1 = bias[nn + 1];
            float v00 = acc[mt][nt][0] + b0;
            float v01 = acc[mt][nt][1] + b1;
            float v10 = acc[mt][nt][2] + b0;
            float v11 = acc[mt][nt][3] + b1;

            if (mode == 0) {
                *(float2*)&C[(size_t)mm * N + nn]       = make_float2(v00, v01);
                *(float2*)&C[(size_t)(mm + 8) * N + nn] = make_float2(v10, v11);
            } else if (mode == 1) {
                // tf32(val * SCALE) at paired columns
                int c0 = colphys(nn), c1 = colphys(nn + 1);
                C[(size_t)mm * DIM + c0]       = f2tf_f(v00 * SCALE_F);
                C[(size_t)mm * DIM + c1]       = f2tf_f(v01 * SCALE_F);
                C[(size_t)(mm + 8) * DIM + c0] = f2tf_f(v10 * SCALE_F);
                C[(size_t)(mm + 8) * DIM + c1] = f2tf_f(v11 * SCALE_F);
            } else if (mode == 2) {
                // kv-cache f32 [kvh][t][d]
                size_t base = (size_t)(nn >> 6) * (T_SEQ * HD) + (nn & 63);
                *(float2*)&C[base + (size_t)mm * HD]       = make_float2(v00, v01);
                *(float2*)&C[base + (size_t)(mm + 8) * HD] = make_float2(v10, v11);
                // tf32 paired copy [kvh][t][d-paired]
                int d = nn & 63;
                int p0 = colphys(d), p1 = colphys(d + 1);
                size_t abase = (size_t)(nn >> 6) * (T_SEQ * HD);
                aux[abase + (size_t)mm * HD + p0]       = f2tf_f(v00);
                aux[abase + (size_t)mm * HD + p1]       = f2tf_f(v01);
                aux[abase + (size_t)(mm + 8) * HD + p0] = f2tf_f(v10);
                aux[abase + (size_t)(mm + 8) * HD + p1] = f2tf_f(v11);
            } else {
                // kv-cache f32
                size_t base = (size_t)(nn >> 6) * (T_SEQ * HD) + (nn & 63);
                *(float2*)&C[base + (size_t)mm * HD]       = make_float2(v00, v01);
                *(float2*)&C[base + (size_t)(mm + 8) * HD] = make_float2(v10, v11);
                // tf32 transposed copy [kvh][d][t-paired], pairing on seq (mm)
                int d = nn & 63;
                size_t abase = (size_t)(nn >> 6) * (HD * T_SEQ);
                int s0 = (mm & ~7) | perm8(mm & 7);
                int s1 = ((mm + 8) & ~7) | perm8(mm & 7);
                aux[abase + (size_t)d * T_SEQ + s0]       = f2tf_f(v00);
                aux[abase + (size_t)(d + 1) * T_SEQ + s0] = f2tf_f(v01);
                aux[abase + (size_t)d * T_SEQ + s1]       = f2tf_f(v10);
                aux[abase + (size_t)(d + 1) * T_SEQ + s1] = f2tf_f(v11);
            }
        }
    }
}

// ---------------------------------------------------------------------------
// TF32 flash attention, cp.async double-buffered K/V, shfl P-relayout.
// CTA = 64 q rows x 1 head, 4 warps. Operands pre-converted to tf32, paired.
// ---------------------------------------------------------------------------
__device__ __forceinline__ void load_kv_tile(float* Kbuf, float* Vbuf,
                                             const float* Kh, const float* Vh,
                                             int kstart, int tid)
{
    int row = tid >> 1;
    int cb = (tid & 1) * 32;
    const float* sK = Kh + (size_t)(kstart + row) * HD + cb;
    const float* sV = Vh + (size_t)row * T_SEQ + kstart + cb;
    unsigned dK = (unsigned)__cvta_generic_to_shared(Kbuf + row * 72 + cb);
    unsigned dV = (unsigned)__cvta_generic_to_shared(Vbuf + row * 72 + cb);
    #pragma unroll
    for (int i = 0; i < 8; i++) CP16(dK + i * 16, sK + i * 4);
    #pragma unroll
    for (int i = 0; i < 8; i++) CP16(dV + i * 16, sV + i * 4);
    CP_COMMIT();
}

__global__ __launch_bounds__(128, 3)
void flash_tf32(const float* __restrict__ Qt,
                const float* __restrict__ Kt,
                const float* __restrict__ Vt,
                float* __restrict__ O)
{
    extern __shared__ float smem[];
    // [2][64][72] each
    float* Kf = smem;
    float* Vf = smem + 2 * 64 * 72;

    int tid  = threadIdx.x;
    int lane = tid & 31;
    int w = tid >> 5;
    int t = lane & 3;
    int g = lane >> 2;
    int qb = (gridDim.x - 1) - blockIdx.x;   // heavy blocks first
    int h = blockIdx.y;
    int kvh = h >> 2;
    int qstart = qb * 64;

    const float* Kh = Kt + (size_t)kvh * T_SEQ * HD;
    const float* Vh = Vt + (size_t)kvh * HD * T_SEQ;

    int r0g = qstart + w * 16 + g;
    int r1g = r0g + 8;

    // Q fragments straight from gmem (pre-scaled, tf32, paired)
    unsigned qf[8][4];
    #pragma unroll
    for (int kt = 0; kt < 8; kt++) {
        uint2 v0 = *(const uint2*)&Qt[(size_t)r0g * DIM + h * HD + kt * 8 + 2 * t];
        uint2 v1 = *(const uint2*)&Qt[(size_t)r1g * DIM + h * HD + kt * 8 + 2 * t];
        qf[kt][0] = v0.x; qf[kt][1] = v1.x; qf[kt][2] = v0.y; qf[kt][3] = v1.y;
    }

    float oacc[8][4];
    #pragma unroll
    for (int nt = 0; nt < 8; nt++)
        #pragma unroll
        for (int i = 0; i < 4; i++) oacc[nt][i] = 0.f;
    float m0 = -1e30f, m1 = -1e30f, l0 = 0.f, l1 = 0.f;

    load_kv_tile(Kf, Vf, Kh, Vh, 0, tid);

    for (int kb = 0; kb <= qb; kb++) {
        int b = kb & 1;
        if (kb < qb) {
            load_kv_tile(Kf + (1 - b) * 64 * 72, Vf + (1 - b) * 64 * 72,
                         Kh, Vh, (kb + 1) * 64, tid);
            CP_WAIT1();
        } else {
            CP_WAIT0();
        }
        __syncthreads();

        const float* Kb = Kf + b * 64 * 72;
        const float* Vb = Vf + b * 64 * 72;
        int kstart = kb * 64;

        // ---- S = Q @ K^T ----
        float sacc[8][4];
        #pragma unroll
        for (int nt = 0; nt < 8; nt++)
            #pragma unroll
            for (int i = 0; i < 4; i++) sacc[nt][i] = 0.f;

        #pragma unroll
        for (int kt = 0; kt < 8; kt++) {
            #pragma unroll
            for (int nt = 0; nt < 8; nt++) {
                uint2 bb = *(const uint2*)&Kb[(nt * 8 + g) * 72 + kt * 8 + 2 * t];
                mma_tf32(sacc[nt], qf[kt], (const unsigned*)&bb);
            }
        }

        // ---- causal mask (diagonal block only) ----
        if (kb == qb) {
            #pragma unroll
            for (int nt = 0; nt < 8; nt++) {
                int c0 = kstart + nt * 8 + 2 * t;
                int c1 = c0 + 1;
                if (c0 > r0g) sacc[nt][0] = -1e30f;
                if (c1 > r0g) sacc[nt][1] = -1e30f;
                if (c0 > r1g) sacc[nt][2] = -1e30f;
                if (c1 > r1g) sacc[nt][3] = -1e30f;
            }
        }

        // ---- online softmax ----
        float mx0 = -1e30f, mx1 = -1e30f;
        #pragma unroll
        for (int nt = 0; nt < 8; nt++) {
            mx0 = fmaxf(mx0, fmaxf(sacc[nt][0], sacc[nt][1]));
            mx1 = fmaxf(mx1, fmaxf(sacc[nt][2], sacc[nt][3]));
        }
        mx0 = fmaxf(mx0, __shfl_xor_sync(0xffffffffu, mx0, 1));
        mx0 = fmaxf(mx0, __shfl_xor_sync(0xffffffffu, mx0, 2));
        mx1 = fmaxf(mx1, __shfl_xor_sync(0xffffffffu, mx1, 1));
        mx1 = fmaxf(mx1, __shfl_xor_sync(0xffffffffu, mx1, 2));

        float nm0 = fmaxf(m0, mx0), nm1 = fmaxf(m1, mx1);
        float alpha0 = __expf(m0 - nm0), alpha1 = __expf(m1 - nm1);
        m0 = nm0; m1 = nm1;

        float rs0 = 0.f, rs1 = 0.f;
        #pragma unroll
        for (int nt = 0; nt < 8; nt++) {
            float p00 = __expf(sacc[nt][0] - nm0);
            float p01 = __expf(sacc[nt][1] - nm0);
            float p10 = __expf(sacc[nt][2] - nm1);
            float p11 = __expf(sacc[nt][3] - nm1);
            rs0 += p00 + p01;
            rs1 += p10 + p11;
            // store tf32 bits back into sacc (shfl sources for relayout)
            sacc[nt][0] = f2tf_f(p00);
            sacc[nt][1] = f2tf_f(p01);
            sacc[nt][2] = f2tf_f(p10);
            sacc[nt][3] = f2tf_f(p11);
        }
        rs0 += __shfl_xor_sync(0xffffffffu, rs0, 1);
        rs0 += __shfl_xor_sync(0xffffffffu, rs0, 2);
        rs1 += __shfl_xor_sync(0xffffffffu, rs1, 1);
        rs1 += __shfl_xor_sync(0xffffffffu, rs1, 2);
        l0 = l0 * alpha0 + rs0;
        l1 = l1 * alpha1 + rs1;

        #pragma unroll
        for (int nt = 0; nt < 8; nt++) {
            oacc[nt][0] *= alpha0;
            oacc[nt][1] *= alpha0;
            oacc[nt][2] *= alpha1;
            oacc[nt][3] *= alpha1;
        }

        // ---- O += P @ V : relayout P C-frag -> A-frag via shfl ----
        int srcA = (lane & ~3) | (t >> 1);
        int srcB = srcA + 2;
        bool sel = (t & 1);
        #pragma unroll
        for (int kt = 0; kt < 8; kt++) {
            float v00 = __shfl_sync(0xffffffffu, sacc[kt][0], srcA);
            float v01 = __shfl_sync(0xffffffffu, sacc[kt][1], srcA);
            float v10 = __shfl_sync(0xffffffffu, sacc[kt][2], srcA);
            float v11 = __shfl_sync(0xffffffffu, sacc[kt][3], srcA);
            float w00 = __shfl_sync(0xffffffffu, sacc[kt][0], srcB);
            float w01 = __shfl_sync(0xffffffffu, sacc[kt][1], srcB);
            float w10 = __shfl_sync(0xffffffffu, sacc[kt][2], srcB);
            float w11 = __shfl_sync(0xffffffffu, sacc[kt][3], srcB);
            unsigned a[4];
            a[0] = __float_as_uint(sel ? v01 : v00);
            a[1] = __float_as_uint(sel ? v11 : v10);
            a[2] = __float_as_uint(sel ? w01 : w00);
            a[3] = __float_as_uint(sel ? w11 : w10);
            #pragma unroll
            for (int nt = 0; nt < 8; nt++) {
                uint2 bb = *(const uint2*)&Vb[(nt * 8 + g) * 72 + kt * 8 + 2 * t];
                mma_tf32(oacc[nt], a, (const unsigned*)&bb);
            }
        }

        __syncthreads();
    }

    // ---- epilogue ----
    float inv0 = 1.f / l0, inv1 = 1.f / l1;
    #pragma unroll
    for (int nt = 0; nt < 8; nt++) {
        int col = h * HD + nt * 8 + 2 * t;
        *(float2*)&O[(size_t)r0g * DIM + col] =
            make_float2(oacc[nt][0] * inv0, oacc[nt][1] * inv0);
        *(float2*)&O[(size_t)r1g * DIM + col] =
            make_float2(oacc[nt][2] * inv1, oacc[nt][3] * inv1);
    }
}

// ---------------------------------------------------------------------------
extern "C" void kernel_launch(void* const* d_in, const int* in_sizes, int n_in,
                              void* d_out, int out_size)
{
    const float* x   = (const float*)d_in[0];
    // d_in[1] = mask (causal) — analytic
    const float* q_w = (const float*)d_in[2];
    const float* q_b = (const float*)d_in[3];
    const float* k_w = (const float*)d_in[4];
    const float* k_b = (const float*)d_in[5];
    const float* v_w = (const float*)d_in[6];
    const float* v_b = (const float*)d_in[7];
    const float* o_w = (const float*)d_in[8];
    const float* o_b = (const float*)d_in[9];

    float* out  = (float*)d_out;
    float* kout = out + (size_t)T_SEQ * DIM;
    float* vout = kout + (size_t)KV_HEADS * T_SEQ * HD;

    float *qtbuf = nullptr, *abuf = nullptr, *ktbuf = nullptr, *vtbuf = nullptr;
    cudaGetSymbolAddress((void**)&qtbuf, g_Qt);
    cudaGetSymbolAddress((void**)&abuf,  g_att);
    cudaGetSymbolAddress((void**)&ktbuf, g_Kt);
    cudaGetSymbolAddress((void**)&vtbuf, g_Vt);

    const int flash_smem = 2 * 2 * 64 * 72 * (int)sizeof(float);  // 73728
    cudaFuncSetAttribute(flash_tf32, cudaFuncAttributeMaxDynamicSharedMemorySize,
                         flash_smem);

    // Q projection -> g_Qt (tf32, scaled, paired)
    gemm_tf32<<<dim3(DIM / 128, T_SEQ / 128), 256>>>(x, q_w, q_b, qtbuf, nullptr,
                                                     T_SEQ, DIM, DIM, 1);
    // K projection -> kout (f32 kv) + g_Kt (tf32 paired)
    gemm_tf32<<<dim3(KV_DIM / 128, T_SEQ / 128), 256>>>(x, k_w, k_b, kout, ktbuf,
                                                        T_SEQ, KV_DIM, DIM, 2);
    // V projection -> vout (f32 kv) + g_Vt (tf32 transposed paired)
    gemm_tf32<<<dim3(KV_DIM / 128, T_SEQ / 128), 256>>>(x, v_w, v_b, vout, vtbuf,
                                                        T_SEQ, KV_DIM, DIM, 3);
    // causal attention -> g_att
    flash_tf32<<<dim3(T_SEQ / 64, HEADS), 128, flash_smem>>>(qtbuf, ktbuf,
                                                             vtbuf, abuf);
    // output projection -> out
    gemm_tf32<<<dim3(DIM / 128, T_SEQ / 128), 256>>>(abuf, o_w, o_b, out, nullptr,
                                                     T_SEQ, DIM, DIM, 0);
}

// round 5
// speedup vs baseline: 3.5496x; 1.1370x over previous
#include <cuda_runtime.h>
#include <math.h>

#define T_SEQ 4096
#define DIM 1024
#define HEADS 16
#define KV_HEADS 4
#define HD 64
#define KV_DIM 256
#define SCALE_F 0.125f
#define QSCALE (0.125f * 1.44269504088896340736f)   // scale * log2(e)

// Scratch (allocation-free rule: __device__ globals)
__device__ float g_Qt[T_SEQ * DIM];                 // tf32 Q*QSCALE, paired cols
__device__ float g_att[T_SEQ * DIM];                // attention output (f32)
__device__ float g_Kt[KV_HEADS * T_SEQ * HD];       // tf32 K, [kvh][t][d-paired]
__device__ float g_Vt[KV_HEADS * T_SEQ * HD];       // tf32 V, [kvh][d][t-paired]

__device__ __forceinline__ unsigned f2tf(float x) {
    unsigned r;
    asm("cvt.rna.tf32.f32 %0, %1;" : "=r"(r) : "f"(x));
    return r;
}
__device__ __forceinline__ float f2tf_f(float x) {
    return __uint_as_float(f2tf(x));
}
__device__ __forceinline__ float ex2f(float x) {
    float y;
    asm("ex2.approx.ftz.f32 %0, %1;" : "=f"(y) : "f"(x));
    return y;
}

__device__ __forceinline__ void mma_tf32(float* c, const unsigned* a, const unsigned* b) {
    asm volatile(
        "mma.sync.aligned.m16n8k8.row.col.f32.tf32.tf32.f32 "
        "{%0,%1,%2,%3}, {%4,%5,%6,%7}, {%8,%9}, {%0,%1,%2,%3};\n"
        : "+f"(c[0]), "+f"(c[1]), "+f"(c[2]), "+f"(c[3])
        : "r"(a[0]), "r"(a[1]), "r"(a[2]), "r"(a[3]),
          "r"(b[0]), "r"(b[1]));
}

// pairing permutation within an 8-column group: logical j -> phys
__device__ __host__ __forceinline__ int perm8(int j) {
    return ((j & 3) << 1) | (j >> 2);
}
__device__ __forceinline__ int colphys(int c) {
    return (c & ~7) | perm8(c & 7);
}

#define CP16(d, s) asm volatile("cp.async.cg.shared.global [%0], [%1], 16;" :: "r"(d), "l"(s))
#define CP_COMMIT() asm volatile("cp.async.commit_group;" ::: "memory")
#define CP_WAIT0() asm volatile("cp.async.wait_group 0;" ::: "memory")
#define CP_WAIT1() asm volatile("cp.async.wait_group 1;" ::: "memory")

// ---------------------------------------------------------------------------
// TF32 GEMM core: C = A[M,1024] @ W[N,1024]^T + bias.  Double-buffered smem,
// register prefetch, one __syncthreads per 32-k step.
// mode 0: f32 store, row stride DIM
// mode 1: Q: tf32(v*QSCALE) paired -> C (row stride DIM)
// mode 2: K: f32 kv-cache -> C, tf32 paired -> aux [kvh][t][d]
// mode 3: V: f32 kv-cache -> C, tf32 transposed paired -> aux [kvh][d][t]
// ---------------------------------------------------------------------------
struct GemmSmem { unsigned A[2][128][40]; unsigned W[2][128][40]; };

__device__ __forceinline__ void gemm_core(
    const float* __restrict__ A,
    const float* __restrict__ W,
    const float* __restrict__ bias,
    float* __restrict__ C,
    float* __restrict__ aux,
    int mb, int n_base, int mode, GemmSmem& sm)
{
    const int Kd = DIM;
    int tid  = threadIdx.x;
    int lane = tid & 31;
    int warp = tid >> 5;
    int wm = warp & 1;
    int wn = warp >> 1;
    int t = lane & 3;
    int g = lane >> 2;
    int frow = tid >> 2;          // 0..63
    int fgrp = tid & 3;           // col group of 8

    float acc[4][4][4];
    #pragma unroll
    for (int mt = 0; mt < 4; mt++)
        #pragma unroll
        for (int nt = 0; nt < 4; nt++)
            #pragma unroll
            for (int i = 0; i < 4; i++) acc[mt][nt][i] = 0.f;

    const float* pa0 = A + (size_t)(mb + frow) * Kd + fgrp * 8;
    const float* pa1 = pa0 + (size_t)64 * Kd;
    const float* pw0 = W + (size_t)(n_base + frow) * Kd + fgrp * 8;
    const float* pw1 = pw0 + (size_t)64 * Kd;

    float4 ra[4], rw[4];
    ra[0] = *(const float4*)pa0; ra[1] = *(const float4*)(pa0 + 4);
    ra[2] = *(const float4*)pa1; ra[3] = *(const float4*)(pa1 + 4);
    rw[0] = *(const float4*)pw0; rw[1] = *(const float4*)(pw0 + 4);
    rw[2] = *(const float4*)pw1; rw[3] = *(const float4*)(pw1 + 4);

    int buf = 0;
    for (int k0 = 0; k0 < Kd; k0 += 32) {
        // paired STS of the prefetched tile
        {
            uint4 x0 = make_uint4(f2tf(ra[0].x), f2tf(ra[1].x), f2tf(ra[0].y), f2tf(ra[1].y));
            uint4 x1 = make_uint4(f2tf(ra[0].z), f2tf(ra[1].z), f2tf(ra[0].w), f2tf(ra[1].w));
            uint4 x2 = make_uint4(f2tf(ra[2].x), f2tf(ra[3].x), f2tf(ra[2].y), f2tf(ra[3].y));
            uint4 x3 = make_uint4(f2tf(ra[2].z), f2tf(ra[3].z), f2tf(ra[2].w), f2tf(ra[3].w));
            *(uint4*)&sm.A[buf][frow][fgrp * 8]          = x0;
            *(uint4*)&sm.A[buf][frow][fgrp * 8 + 4]      = x1;
            *(uint4*)&sm.A[buf][frow + 64][fgrp * 8]     = x2;
            *(uint4*)&sm.A[buf][frow + 64][fgrp * 8 + 4] = x3;
            uint4 y0 = make_uint4(f2tf(rw[0].x), f2tf(rw[1].x), f2tf(rw[0].y), f2tf(rw[1].y));
            uint4 y1 = make_uint4(f2tf(rw[0].z), f2tf(rw[1].z), f2tf(rw[0].w), f2tf(rw[1].w));
            uint4 y2 = make_uint4(f2tf(rw[2].x), f2tf(rw[3].x), f2tf(rw[2].y), f2tf(rw[3].y));
            uint4 y3 = make_uint4(f2tf(rw[2].z), f2tf(rw[3].z), f2tf(rw[2].w), f2tf(rw[3].w));
            *(uint4*)&sm.W[buf][frow][fgrp * 8]          = y0;
            *(uint4*)&sm.W[buf][frow][fgrp * 8 + 4]      = y1;
            *(uint4*)&sm.W[buf][frow + 64][fgrp * 8]     = y2;
            *(uint4*)&sm.W[buf][frow + 64][fgrp * 8 + 4] = y3;
        }
        __syncthreads();

        if (k0 + 32 < Kd) {
            int ko = k0 + 32;
            ra[0] = *(const float4*)(pa0 + ko); ra[1] = *(const float4*)(pa0 + ko + 4);
            ra[2] = *(const float4*)(pa1 + ko); ra[3] = *(const float4*)(pa1 + ko + 4);
            rw[0] = *(const float4*)(pw0 + ko); rw[1] = *(const float4*)(pw0 + ko + 4);
            rw[2] = *(const float4*)(pw1 + ko); rw[3] = *(const float4*)(pw1 + ko + 4);
        }

        #pragma unroll
        for (int kt = 0; kt < 4; kt++) {
            unsigned a[4][4], b[4][2];
            #pragma unroll
            for (int mt = 0; mt < 4; mt++) {
                int row = wm * 64 + mt * 16 + g;
                uint2 v0 = *(uint2*)&sm.A[buf][row][kt * 8 + 2 * t];
                uint2 v1 = *(uint2*)&sm.A[buf][row + 8][kt * 8 + 2 * t];
                a[mt][0] = v0.x; a[mt][1] = v1.x; a[mt][2] = v0.y; a[mt][3] = v1.y;
            }
            #pragma unroll
            for (int nt = 0; nt < 4; nt++) {
                int bn = wn * 32 + nt * 8 + g;
                uint2 vb = *(uint2*)&sm.W[buf][bn][kt * 8 + 2 * t];
                b[nt][0] = vb.x; b[nt][1] = vb.y;
            }
            #pragma unroll
            for (int mt = 0; mt < 4; mt++)
                #pragma unroll
                for (int nt = 0; nt < 4; nt++)
                    mma_tf32(acc[mt][nt], a[mt], b[nt]);
        }
        buf ^= 1;
    }

    #pragma unroll
    for (int mt = 0; mt < 4; mt++) {
        int mm = mb + wm * 64 + mt * 16 + g;
        #pragma unroll
        for (int nt = 0; nt < 4; nt++) {
            int nn = n_base + wn * 32 + nt * 8 + 2 * t;
            float b0 = bias[nn], b1 = bias[nn + 1];
            float v00 = acc[mt][nt][0] + b0;
            float v01 = acc[mt][nt][1] + b1;
            float v10 = acc[mt][nt][2] + b0;
            float v11 = acc[mt][nt][3] + b1;

            if (mode == 0) {
                *(float2*)&C[(size_t)mm * DIM + nn]       = make_float2(v00, v01);
                *(float2*)&C[(size_t)(mm + 8) * DIM + nn] = make_float2(v10, v11);
            } else if (mode == 1) {
                int c0 = colphys(nn), c1 = colphys(nn + 1);
                C[(size_t)mm * DIM + c0]       = f2tf_f(v00 * QSCALE);
                C[(size_t)mm * DIM + c1]       = f2tf_f(v01 * QSCALE);
                C[(size_t)(mm + 8) * DIM + c0] = f2tf_f(v10 * QSCALE);
                C[(size_t)(mm + 8) * DIM + c1] = f2tf_f(v11 * QSCALE);
            } else if (mode == 2) {
                size_t base = (size_t)(nn >> 6) * (T_SEQ * HD) + (nn & 63);
                *(float2*)&C[base + (size_t)mm * HD]       = make_float2(v00, v01);
                *(float2*)&C[base + (size_t)(mm + 8) * HD] = make_float2(v10, v11);
                int d = nn & 63;
                int p0 = colphys(d), p1 = colphys(d + 1);
                size_t abase = (size_t)(nn >> 6) * (T_SEQ * HD);
                aux[abase + (size_t)mm * HD + p0]       = f2tf_f(v00);
                aux[abase + (size_t)mm * HD + p1]       = f2tf_f(v01);
                aux[abase + (size_t)(mm + 8) * HD + p0] = f2tf_f(v10);
                aux[abase + (size_t)(mm + 8) * HD + p1] = f2tf_f(v11);
            } else {
                size_t base = (size_t)(nn >> 6) * (T_SEQ * HD) + (nn & 63);
                *(float2*)&C[base + (size_t)mm * HD]       = make_float2(v00, v01);
                *(float2*)&C[base + (size_t)(mm + 8) * HD] = make_float2(v10, v11);
                int d = nn & 63;
                size_t abase = (size_t)(nn >> 6) * (HD * T_SEQ);
                int s0 = (mm & ~7) | perm8(mm & 7);
                int s1 = ((mm + 8) & ~7) | perm8(mm & 7);
                aux[abase + (size_t)d * T_SEQ + s0]       = f2tf_f(v00);
                aux[abase + (size_t)(d + 1) * T_SEQ + s0] = f2tf_f(v01);
                aux[abase + (size_t)d * T_SEQ + s1]       = f2tf_f(v10);
                aux[abase + (size_t)(d + 1) * T_SEQ + s1] = f2tf_f(v11);
            }
        }
    }
}

__global__ __launch_bounds__(256, 2)
void gemm_qkv(const float* __restrict__ x,
              const float* __restrict__ qw, const float* __restrict__ qb,
              const float* __restrict__ kw, const float* __restrict__ kb,
              const float* __restrict__ vw, const float* __restrict__ vb,
              float* __restrict__ qt,
              float* __restrict__ kc, float* __restrict__ ktt,
              float* __restrict__ vc, float* __restrict__ vtt)
{
    extern __shared__ GemmSmem sgm[];
    int bx = blockIdx.x;
    int mb = blockIdx.y * 128;
    if (bx < 8)
        gemm_core(x, qw, qb, qt, nullptr, mb, bx * 128, 1, sgm[0]);
    else if (bx < 10)
        gemm_core(x, kw, kb, kc, ktt, mb, (bx - 8) * 128, 2, sgm[0]);
    else
        gemm_core(x, vw, vb, vc, vtt, mb, (bx - 10) * 128, 3, sgm[0]);
}

__global__ __launch_bounds__(256, 2)
void gemm_o(const float* __restrict__ A, const float* __restrict__ w,
            const float* __restrict__ b, float* __restrict__ C)
{
    extern __shared__ GemmSmem sgm[];
    gemm_core(A, w, b, C, nullptr, blockIdx.y * 128, blockIdx.x * 128, 0, sgm[0]);
}

// ---------------------------------------------------------------------------
// TF32 flash attention: cp.async double-buffered K/V, per-kt fused
// exp/relayout/PV (softmax overlapped with tensor work), exp2-based.
// ---------------------------------------------------------------------------
__device__ __forceinline__ void load_kv_tile(float* Kbuf, float* Vbuf,
                                             const float* Kh, const float* Vh,
                                             int kstart, int tid)
{
    int row = tid >> 1;
    int cb = (tid & 1) * 32;
    const float* sK = Kh + (size_t)(kstart + row) * HD + cb;
    const float* sV = Vh + (size_t)row * T_SEQ + kstart + cb;
    unsigned dK = (unsigned)__cvta_generic_to_shared(Kbuf + row * 72 + cb);
    unsigned dV = (unsigned)__cvta_generic_to_shared(Vbuf + row * 72 + cb);
    #pragma unroll
    for (int i = 0; i < 8; i++) CP16(dK + i * 16, sK + i * 4);
    #pragma unroll
    for (int i = 0; i < 8; i++) CP16(dV + i * 16, sV + i * 4);
    CP_COMMIT();
}

__global__ __launch_bounds__(128, 3)
void flash_tf32(const float* __restrict__ Qt,
                const float* __restrict__ Kt,
                const float* __restrict__ Vt,
                float* __restrict__ O)
{
    extern __shared__ float smem[];
    float* Kf = smem;                 // [2][64][72]
    float* Vf = smem + 2 * 64 * 72;   // [2][64][72]

    int tid  = threadIdx.x;
    int lane = tid & 31;
    int w = tid >> 5;
    int t = lane & 3;
    int g = lane >> 2;
    int qb = (gridDim.x - 1) - blockIdx.x;   // heavy blocks first
    int h = blockIdx.y;
    int kvh = h >> 2;
    int qstart = qb * 64;

    const float* Kh = Kt + (size_t)kvh * T_SEQ * HD;
    const float* Vh = Vt + (size_t)kvh * HD * T_SEQ;

    int r0g = qstart + w * 16 + g;
    int r1g = r0g + 8;

    unsigned qf[8][4];
    #pragma unroll
    for (int kt = 0; kt < 8; kt++) {
        uint2 v0 = *(const uint2*)&Qt[(size_t)r0g * DIM + h * HD + kt * 8 + 2 * t];
        uint2 v1 = *(const uint2*)&Qt[(size_t)r1g * DIM + h * HD + kt * 8 + 2 * t];
        qf[kt][0] = v0.x; qf[kt][1] = v1.x; qf[kt][2] = v0.y; qf[kt][3] = v1.y;
    }

    float oacc[8][4];
    #pragma unroll
    for (int nt = 0; nt < 8; nt++)
        #pragma unroll
        for (int i = 0; i < 4; i++) oacc[nt][i] = 0.f;
    float m0 = -1e30f, m1 = -1e30f, l0 = 0.f, l1 = 0.f;

    int srcA = (lane & ~3) | (t >> 1);
    int srcB = srcA + 2;
    bool sel = (t & 1);

    load_kv_tile(Kf, Vf, Kh, Vh, 0, tid);

    for (int kb = 0; kb <= qb; kb++) {
        int b = kb & 1;
        if (kb < qb) {
            load_kv_tile(Kf + (1 - b) * 64 * 72, Vf + (1 - b) * 64 * 72,
                         Kh, Vh, (kb + 1) * 64, tid);
            CP_WAIT1();
        } else {
            CP_WAIT0();
        }
        __syncthreads();

        const float* Kb = Kf + b * 64 * 72;
        const float* Vb = Vf + b * 64 * 72;
        int kstart = kb * 64;

        // ---- S = Q @ K^T (scores already in log2e units via QSCALE) ----
        float sacc[8][4];
        #pragma unroll
        for (int nt = 0; nt < 8; nt++)
            #pragma unroll
            for (int i = 0; i < 4; i++) sacc[nt][i] = 0.f;

        #pragma unroll
        for (int kt = 0; kt < 8; kt++) {
            #pragma unroll
            for (int nt = 0; nt < 8; nt++) {
                uint2 bb = *(const uint2*)&Kb[(nt * 8 + g) * 72 + kt * 8 + 2 * t];
                mma_tf32(sacc[nt], qf[kt], (const unsigned*)&bb);
            }
        }

        if (kb == qb) {
            #pragma unroll
            for (int nt = 0; nt < 8; nt++) {
                int c0 = kstart + nt * 8 + 2 * t;
                int c1 = c0 + 1;
                if (c0 > r0g) sacc[nt][0] = -1e30f;
                if (c1 > r0g) sacc[nt][1] = -1e30f;
                if (c0 > r1g) sacc[nt][2] = -1e30f;
                if (c1 > r1g) sacc[nt][3] = -1e30f;
            }
        }

        // ---- row max ----
        float mx0 = -1e30f, mx1 = -1e30f;
        #pragma unroll
        for (int nt = 0; nt < 8; nt++) {
            mx0 = fmaxf(mx0, fmaxf(sacc[nt][0], sacc[nt][1]));
            mx1 = fmaxf(mx1, fmaxf(sacc[nt][2], sacc[nt][3]));
        }
        mx0 = fmaxf(mx0, __shfl_xor_sync(0xffffffffu, mx0, 1));
        mx0 = fmaxf(mx0, __shfl_xor_sync(0xffffffffu, mx0, 2));
        mx1 = fmaxf(mx1, __shfl_xor_sync(0xffffffffu, mx1, 1));
        mx1 = fmaxf(mx1, __shfl_xor_sync(0xffffffffu, mx1, 2));

        float nm0 = fmaxf(m0, mx0), nm1 = fmaxf(m1, mx1);
        float alpha0 = ex2f(m0 - nm0), alpha1 = ex2f(m1 - nm1);
        m0 = nm0; m1 = nm1;

        #pragma unroll
        for (int nt = 0; nt < 8; nt++) {
            oacc[nt][0] *= alpha0;
            oacc[nt][1] *= alpha0;
            oacc[nt][2] *= alpha1;
            oacc[nt][3] *= alpha1;
        }

        // ---- fused exp + relayout + PV per kt ----
        float rs0 = 0.f, rs1 = 0.f;
        #pragma unroll
        for (int kt = 0; kt < 8; kt++) {
            float p00 = ex2f(sacc[kt][0] - nm0);
            float p01 = ex2f(sacc[kt][1] - nm0);
            float p10 = ex2f(sacc[kt][2] - nm1);
            float p11 = ex2f(sacc[kt][3] - nm1);
            rs0 += p00 + p01;
            rs1 += p10 + p11;
            float q00 = f2tf_f(p00), q01 = f2tf_f(p01);
            float q10 = f2tf_f(p10), q11 = f2tf_f(p11);
            float v00 = __shfl_sync(0xffffffffu, q00, srcA);
            float v01 = __shfl_sync(0xffffffffu, q01, srcA);
            float v10 = __shfl_sync(0xffffffffu, q10, srcA);
            float v11 = __shfl_sync(0xffffffffu, q11, srcA);
            float w00 = __shfl_sync(0xffffffffu, q00, srcB);
            float w01 = __shfl_sync(0xffffffffu, q01, srcB);
            float w10 = __shfl_sync(0xffffffffu, q10, srcB);
            float w11 = __shfl_sync(0xffffffffu, q11, srcB);
            unsigned a[4];
            a[0] = __float_as_uint(sel ? v01 : v00);
            a[1] = __float_as_uint(sel ? v11 : v10);
            a[2] = __float_as_uint(sel ? w01 : w00);
            a[3] = __float_as_uint(sel ? w11 : w10);
            #pragma unroll
            for (int nt = 0; nt < 8; nt++) {
                uint2 bb = *(const uint2*)&Vb[(nt * 8 + g) * 72 + kt * 8 + 2 * t];
                mma_tf32(oacc[nt], a, (const unsigned*)&bb);
            }
        }
        rs0 += __shfl_xor_sync(0xffffffffu, rs0, 1);
        rs0 += __shfl_xor_sync(0xffffffffu, rs0, 2);
        rs1 += __shfl_xor_sync(0xffffffffu, rs1, 1);
        rs1 += __shfl_xor_sync(0xffffffffu, rs1, 2);
        l0 = l0 * alpha0 + rs0;
        l1 = l1 * alpha1 + rs1;

        __syncthreads();
    }

    float inv0 = 1.f / l0, inv1 = 1.f / l1;
    #pragma unroll
    for (int nt = 0; nt < 8; nt++) {
        int col = h * HD + nt * 8 + 2 * t;
        *(float2*)&O[(size_t)r0g * DIM + col] =
            make_float2(oacc[nt][0] * inv0, oacc[nt][1] * inv0);
        *(float2*)&O[(size_t)r1g * DIM + col] =
            make_float2(oacc[nt][2] * inv1, oacc[nt][3] * inv1);
    }
}

// ---------------------------------------------------------------------------
extern "C" void kernel_launch(void* const* d_in, const int* in_sizes, int n_in,
                              void* d_out, int out_size)
{
    const float* x   = (const float*)d_in[0];
    // d_in[1] = mask (causal) — analytic
    const float* q_w = (const float*)d_in[2];
    const float* q_b = (const float*)d_in[3];
    const float* k_w = (const float*)d_in[4];
    const float* k_b = (const float*)d_in[5];
    const float* v_w = (const float*)d_in[6];
    const float* v_b = (const float*)d_in[7];
    const float* o_w = (const float*)d_in[8];
    const float* o_b = (const float*)d_in[9];

    float* out  = (float*)d_out;
    float* kout = out + (size_t)T_SEQ * DIM;
    float* vout = kout + (size_t)KV_HEADS * T_SEQ * HD;

    float *qtbuf = nullptr, *abuf = nullptr, *ktbuf = nullptr, *vtbuf = nullptr;
    cudaGetSymbolAddress((void**)&qtbuf, g_Qt);
    cudaGetSymbolAddress((void**)&abuf,  g_att);
    cudaGetSymbolAddress((void**)&ktbuf, g_Kt);
    cudaGetSymbolAddress((void**)&vtbuf, g_Vt);

    const int gemm_smem  = (int)sizeof(GemmSmem);                 // 81920
    const int flash_smem = 2 * 2 * 64 * 72 * (int)sizeof(float);  // 73728
    cudaFuncSetAttribute(gemm_qkv, cudaFuncAttributeMaxDynamicSharedMemorySize, gemm_smem);
    cudaFuncSetAttribute(gemm_o,   cudaFuncAttributeMaxDynamicSharedMemorySize, gemm_smem);
    cudaFuncSetAttribute(flash_tf32, cudaFuncAttributeMaxDynamicSharedMemorySize, flash_smem);

    // fused Q/K/V projections (fills the chip: 384 CTAs)
    gemm_qkv<<<dim3(12, 32), 256, gemm_smem>>>(x, q_w, q_b, k_w, k_b, v_w, v_b,
                                               qtbuf, kout, ktbuf, vout, vtbuf);
    // causal attention -> g_att
    flash_tf32<<<dim3(T_SEQ / 64, HEADS), 128, flash_smem>>>(qtbuf, ktbuf,
                                                             vtbuf, abuf);
    // output projection -> out
    gemm_o<<<dim3(8, 32), 256, gemm_smem>>>(abuf, o_w, o_b, out);
}

// round 6
// speedup vs baseline: 4.1363x; 1.1653x over previous
#include <cuda_runtime.h>
#include <math.h>

#define T_SEQ 4096
#define DIM 1024
#define HEADS 16
#define KV_HEADS 4
#define HD 64
#define KV_DIM 256
#define SCALE_F 0.125f
#define QSCALE (0.125f * 1.44269504088896340736f)   // scale * log2(e)

// Scratch (allocation-free rule: __device__ globals)
__device__ float g_Qt[T_SEQ * DIM];                 // tf32 Q*QSCALE, paired cols
__device__ float g_att[T_SEQ * DIM];                // attention output (f32)
__device__ float g_Kt[KV_HEADS * T_SEQ * HD];       // tf32 K, [kvh][t][d-paired]
__device__ float g_Vt[KV_HEADS * T_SEQ * HD];       // tf32 V, [kvh][d][t-paired]

__device__ __forceinline__ unsigned f2tf(float x) {
    unsigned r;
    asm("cvt.rna.tf32.f32 %0, %1;" : "=r"(r) : "f"(x));
    return r;
}
__device__ __forceinline__ float f2tf_f(float x) {
    return __uint_as_float(f2tf(x));
}
__device__ __forceinline__ float ex2f(float x) {
    float y;
    asm("ex2.approx.ftz.f32 %0, %1;" : "=f"(y) : "f"(x));
    return y;
}

__device__ __forceinline__ void mma_tf32(float* c, const unsigned* a, const unsigned* b) {
    asm volatile(
        "mma.sync.aligned.m16n8k8.row.col.f32.tf32.tf32.f32 "
        "{%0,%1,%2,%3}, {%4,%5,%6,%7}, {%8,%9}, {%0,%1,%2,%3};\n"
        : "+f"(c[0]), "+f"(c[1]), "+f"(c[2]), "+f"(c[3])
        : "r"(a[0]), "r"(a[1]), "r"(a[2]), "r"(a[3]),
          "r"(b[0]), "r"(b[1]));
}

// pairing permutation within an 8-column group: logical j -> phys
__device__ __host__ __forceinline__ int perm8(int j) {
    return ((j & 3) << 1) | (j >> 2);
}
__device__ __forceinline__ int colphys(int c) {
    return (c & ~7) | perm8(c & 7);
}

#define CP16(d, s) asm volatile("cp.async.cg.shared.global [%0], [%1], 16;" :: "r"(d), "l"(s))
#define CP_COMMIT() asm volatile("cp.async.commit_group;" ::: "memory")
#define CP_WAIT0() asm volatile("cp.async.wait_group 0;" ::: "memory")
#define CP_WAIT1() asm volatile("cp.async.wait_group 1;" ::: "memory")

// ---------------------------------------------------------------------------
// TF32 GEMM core: C = A[M,1024] @ W[N,1024]^T + bias.  Double-buffered smem,
// register prefetch, one __syncthreads per 32-k step.
// mode 0: f32 store, row stride DIM
// mode 1: Q: tf32(v*QSCALE) paired -> C (row stride DIM)
// mode 2: K: f32 kv-cache -> C, tf32 paired -> aux [kvh][t][d]
// mode 3: V: f32 kv-cache -> C, tf32 transposed paired -> aux [kvh][d][t]
// ---------------------------------------------------------------------------
struct GemmSmem { unsigned A[2][128][40]; unsigned W[2][128][40]; };

__device__ __forceinline__ void gemm_core(
    const float* __restrict__ A,
    const float* __restrict__ W,
    const float* __restrict__ bias,
    float* __restrict__ C,
    float* __restrict__ aux,
    int mb, int n_base, int mode, GemmSmem& sm)
{
    const int Kd = DIM;
    int tid  = threadIdx.x;
    int lane = tid & 31;
    int warp = tid >> 5;
    int wm = warp & 1;
    int wn = warp >> 1;
    int t = lane & 3;
    int g = lane >> 2;
    int frow = tid >> 2;          // 0..63
    int fgrp = tid & 3;           // col group of 8

    float acc[4][4][4];
    #pragma unroll
    for (int mt = 0; mt < 4; mt++)
        #pragma unroll
        for (int nt = 0; nt < 4; nt++)
            #pragma unroll
            for (int i = 0; i < 4; i++) acc[mt][nt][i] = 0.f;

    const float* pa0 = A + (size_t)(mb + frow) * Kd + fgrp * 8;
    const float* pa1 = pa0 + (size_t)64 * Kd;
    const float* pw0 = W + (size_t)(n_base + frow) * Kd + fgrp * 8;
    const float* pw1 = pw0 + (size_t)64 * Kd;

    float4 ra[4], rw[4];
    ra[0] = *(const float4*)pa0; ra[1] = *(const float4*)(pa0 + 4);
    ra[2] = *(const float4*)pa1; ra[3] = *(const float4*)(pa1 + 4);
    rw[0] = *(const float4*)pw0; rw[1] = *(const float4*)(pw0 + 4);
    rw[2] = *(const float4*)pw1; rw[3] = *(const float4*)(pw1 + 4);

    int buf = 0;
    for (int k0 = 0; k0 < Kd; k0 += 32) {
        {
            uint4 x0 = make_uint4(f2tf(ra[0].x), f2tf(ra[1].x), f2tf(ra[0].y), f2tf(ra[1].y));
            uint4 x1 = make_uint4(f2tf(ra[0].z), f2tf(ra[1].z), f2tf(ra[0].w), f2tf(ra[1].w));
            uint4 x2 = make_uint4(f2tf(ra[2].x), f2tf(ra[3].x), f2tf(ra[2].y), f2tf(ra[3].y));
            uint4 x3 = make_uint4(f2tf(ra[2].z), f2tf(ra[3].z), f2tf(ra[2].w), f2tf(ra[3].w));
            *(uint4*)&sm.A[buf][frow][fgrp * 8]          = x0;
            *(uint4*)&sm.A[buf][frow][fgrp * 8 + 4]      = x1;
            *(uint4*)&sm.A[buf][frow + 64][fgrp * 8]     = x2;
            *(uint4*)&sm.A[buf][frow + 64][fgrp * 8 + 4] = x3;
            uint4 y0 = make_uint4(f2tf(rw[0].x), f2tf(rw[1].x), f2tf(rw[0].y), f2tf(rw[1].y));
            uint4 y1 = make_uint4(f2tf(rw[0].z), f2tf(rw[1].z), f2tf(rw[0].w), f2tf(rw[1].w));
            uint4 y2 = make_uint4(f2tf(rw[2].x), f2tf(rw[3].x), f2tf(rw[2].y), f2tf(rw[3].y));
            uint4 y3 = make_uint4(f2tf(rw[2].z), f2tf(rw[3].z), f2tf(rw[2].w), f2tf(rw[3].w));
            *(uint4*)&sm.W[buf][frow][fgrp * 8]          = y0;
            *(uint4*)&sm.W[buf][frow][fgrp * 8 + 4]      = y1;
            *(uint4*)&sm.W[buf][frow + 64][fgrp * 8]     = y2;
            *(uint4*)&sm.W[buf][frow + 64][fgrp * 8 + 4] = y3;
        }
        __syncthreads();

        if (k0 + 32 < Kd) {
            int ko = k0 + 32;
            ra[0] = *(const float4*)(pa0 + ko); ra[1] = *(const float4*)(pa0 + ko + 4);
            ra[2] = *(const float4*)(pa1 + ko); ra[3] = *(const float4*)(pa1 + ko + 4);
            rw[0] = *(const float4*)(pw0 + ko); rw[1] = *(const float4*)(pw0 + ko + 4);
            rw[2] = *(const float4*)(pw1 + ko); rw[3] = *(const float4*)(pw1 + ko + 4);
        }

        #pragma unroll
        for (int kt = 0; kt < 4; kt++) {
            unsigned a[4][4], b[4][2];
            #pragma unroll
            for (int mt = 0; mt < 4; mt++) {
                int row = wm * 64 + mt * 16 + g;
                uint2 v0 = *(uint2*)&sm.A[buf][row][kt * 8 + 2 * t];
                uint2 v1 = *(uint2*)&sm.A[buf][row + 8][kt * 8 + 2 * t];
                a[mt][0] = v0.x; a[mt][1] = v1.x; a[mt][2] = v0.y; a[mt][3] = v1.y;
            }
            #pragma unroll
            for (int nt = 0; nt < 4; nt++) {
                int bn = wn * 32 + nt * 8 + g;
                uint2 vb = *(uint2*)&sm.W[buf][bn][kt * 8 + 2 * t];
                b[nt][0] = vb.x; b[nt][1] = vb.y;
            }
            #pragma unroll
            for (int mt = 0; mt < 4; mt++)
                #pragma unroll
                for (int nt = 0; nt < 4; nt++)
                    mma_tf32(acc[mt][nt], a[mt], b[nt]);
        }
        buf ^= 1;
    }

    #pragma unroll
    for (int mt = 0; mt < 4; mt++) {
        int mm = mb + wm * 64 + mt * 16 + g;
        #pragma unroll
        for (int nt = 0; nt < 4; nt++) {
            int nn = n_base + wn * 32 + nt * 8 + 2 * t;
            float b0 = bias[nn], b1 = bias[nn + 1];
            float v00 = acc[mt][nt][0] + b0;
            float v01 = acc[mt][nt][1] + b1;
            float v10 = acc[mt][nt][2] + b0;
            float v11 = acc[mt][nt][3] + b1;

            if (mode == 0) {
                *(float2*)&C[(size_t)mm * DIM + nn]       = make_float2(v00, v01);
                *(float2*)&C[(size_t)(mm + 8) * DIM + nn] = make_float2(v10, v11);
            } else if (mode == 1) {
                int c0 = colphys(nn), c1 = colphys(nn + 1);
                C[(size_t)mm * DIM + c0]       = f2tf_f(v00 * QSCALE);
                C[(size_t)mm * DIM + c1]       = f2tf_f(v01 * QSCALE);
                C[(size_t)(mm + 8) * DIM + c0] = f2tf_f(v10 * QSCALE);
                C[(size_t)(mm + 8) * DIM + c1] = f2tf_f(v11 * QSCALE);
            } else if (mode == 2) {
                size_t base = (size_t)(nn >> 6) * (T_SEQ * HD) + (nn & 63);
                *(float2*)&C[base + (size_t)mm * HD]       = make_float2(v00, v01);
                *(float2*)&C[base + (size_t)(mm + 8) * HD] = make_float2(v10, v11);
                int d = nn & 63;
                int p0 = colphys(d), p1 = colphys(d + 1);
                size_t abase = (size_t)(nn >> 6) * (T_SEQ * HD);
                aux[abase + (size_t)mm * HD + p0]       = f2tf_f(v00);
                aux[abase + (size_t)mm * HD + p1]       = f2tf_f(v01);
                aux[abase + (size_t)(mm + 8) * HD + p0] = f2tf_f(v10);
                aux[abase + (size_t)(mm + 8) * HD + p1] = f2tf_f(v11);
            } else {
                size_t base = (size_t)(nn >> 6) * (T_SEQ * HD) + (nn & 63);
                *(float2*)&C[base + (size_t)mm * HD]       = make_float2(v00, v01);
                *(float2*)&C[base + (size_t)(mm + 8) * HD] = make_float2(v10, v11);
                int d = nn & 63;
                size_t abase = (size_t)(nn >> 6) * (HD * T_SEQ);
                int s0 = (mm & ~7) | perm8(mm & 7);
                int s1 = ((mm + 8) & ~7) | perm8(mm & 7);
                aux[abase + (size_t)d * T_SEQ + s0]       = f2tf_f(v00);
                aux[abase + (size_t)(d + 1) * T_SEQ + s0] = f2tf_f(v01);
                aux[abase + (size_t)d * T_SEQ + s1]       = f2tf_f(v10);
                aux[abase + (size_t)(d + 1) * T_SEQ + s1] = f2tf_f(v11);
            }
        }
    }
}

__global__ __launch_bounds__(256, 2)
void gemm_qkv(const float* __restrict__ x,
              const float* __restrict__ qw, const float* __restrict__ qb,
              const float* __restrict__ kw, const float* __restrict__ kb,
              const float* __restrict__ vw, const float* __restrict__ vb,
              float* __restrict__ qt,
              float* __restrict__ kc, float* __restrict__ ktt,
              float* __restrict__ vc, float* __restrict__ vtt)
{
    extern __shared__ GemmSmem sgm[];
    int bx = blockIdx.x;
    int mb = blockIdx.y * 128;
    if (bx < 8)
        gemm_core(x, qw, qb, qt, nullptr, mb, bx * 128, 1, sgm[0]);
    else if (bx < 10)
        gemm_core(x, kw, kb, kc, ktt, mb, (bx - 8) * 128, 2, sgm[0]);
    else
        gemm_core(x, vw, vb, vc, vtt, mb, (bx - 10) * 128, 3, sgm[0]);
}

__global__ __launch_bounds__(256, 2)
void gemm_o(const float* __restrict__ A, const float* __restrict__ w,
            const float* __restrict__ b, float* __restrict__ C)
{
    extern __shared__ GemmSmem sgm[];
    gemm_core(A, w, b, C, nullptr, blockIdx.y * 128, blockIdx.x * 128, 0, sgm[0]);
}

// ---------------------------------------------------------------------------
// TF32 flash attention, FA2-style: Br=128, 4 warps x 32 q-rows (2 M-tiles
// per warp). Every K/V B-fragment LDS feeds 2 MMAs. cp.async double-buffer.
// ---------------------------------------------------------------------------
__device__ __forceinline__ void load_kv_tile(float* Kbuf, float* Vbuf,
                                             const float* Kh, const float* Vh,
                                             int kstart, int tid)
{
    int row = tid >> 1;
    int cb = (tid & 1) * 32;
    const float* sK = Kh + (size_t)(kstart + row) * HD + cb;
    const float* sV = Vh + (size_t)row * T_SEQ + kstart + cb;
    unsigned dK = (unsigned)__cvta_generic_to_shared(Kbuf + row * 72 + cb);
    unsigned dV = (unsigned)__cvta_generic_to_shared(Vbuf + row * 72 + cb);
    #pragma unroll
    for (int i = 0; i < 8; i++) CP16(dK + i * 16, sK + i * 4);
    #pragma unroll
    for (int i = 0; i < 8; i++) CP16(dV + i * 16, sV + i * 4);
    CP_COMMIT();
}

__global__ __launch_bounds__(128)
void flash_tf32(const float* __restrict__ Qt,
                const float* __restrict__ Kt,
                const float* __restrict__ Vt,
                float* __restrict__ O)
{
    extern __shared__ float smem[];
    float* Kf = smem;                 // [2][64][72]
    float* Vf = smem + 2 * 64 * 72;   // [2][64][72]

    int tid  = threadIdx.x;
    int lane = tid & 31;
    int w = tid >> 5;
    int t = lane & 3;
    int g = lane >> 2;
    int qbi = (gridDim.x - 1) - blockIdx.x;   // heavy blocks first, 0..31
    int h = blockIdx.y;
    int kvh = h >> 2;
    int qstart = qbi * 128;

    const float* Kh = Kt + (size_t)kvh * T_SEQ * HD;
    const float* Vh = Vt + (size_t)kvh * HD * T_SEQ;

    // per-warp rows: mt-tile mt covers rows qstart + w*32 + mt*16 + {g, g+8}
    int r0g[2], r1g[2];
    #pragma unroll
    for (int mt = 0; mt < 2; mt++) {
        r0g[mt] = qstart + w * 32 + mt * 16 + g;
        r1g[mt] = r0g[mt] + 8;
    }

    // Q fragments (pre-scaled tf32, paired cols) straight from gmem
    unsigned qf[2][8][4];
    #pragma unroll
    for (int mt = 0; mt < 2; mt++)
        #pragma unroll
        for (int kt = 0; kt < 8; kt++) {
            uint2 v0 = *(const uint2*)&Qt[(size_t)r0g[mt] * DIM + h * HD + kt * 8 + 2 * t];
            uint2 v1 = *(const uint2*)&Qt[(size_t)r1g[mt] * DIM + h * HD + kt * 8 + 2 * t];
            qf[mt][kt][0] = v0.x; qf[mt][kt][1] = v1.x;
            qf[mt][kt][2] = v0.y; qf[mt][kt][3] = v1.y;
        }

    float oacc[2][8][4];
    #pragma unroll
    for (int mt = 0; mt < 2; mt++)
        #pragma unroll
        for (int nt = 0; nt < 8; nt++)
            #pragma unroll
            for (int i = 0; i < 4; i++) oacc[mt][nt][i] = 0.f;
    float m0[2] = {-1e30f, -1e30f}, m1[2] = {-1e30f, -1e30f};
    float l0[2] = {0.f, 0.f}, l1[2] = {0.f, 0.f};

    int srcA = (lane & ~3) | (t >> 1);
    int srcB = srcA + 2;
    bool sel = (t & 1);

    int nkb = 2 * qbi + 2;
    load_kv_tile(Kf, Vf, Kh, Vh, 0, tid);

    for (int kb = 0; kb < nkb; kb++) {
        int b = kb & 1;
        if (kb + 1 < nkb) {
            load_kv_tile(Kf + (1 - b) * 64 * 72, Vf + (1 - b) * 64 * 72,
                         Kh, Vh, (kb + 1) * 64, tid);
            CP_WAIT1();
        } else {
            CP_WAIT0();
        }
        __syncthreads();

        const float* Kb = Kf + b * 64 * 72;
        const float* Vb = Vf + b * 64 * 72;
        int kstart = kb * 64;

        // ---- S = Q @ K^T : 128 LDS.64, 256 MMA (B reused across 2 M-tiles)
        float sacc[2][8][4];
        #pragma unroll
        for (int mt = 0; mt < 2; mt++)
            #pragma unroll
            for (int nt = 0; nt < 8; nt++)
                #pragma unroll
                for (int i = 0; i < 4; i++) sacc[mt][nt][i] = 0.f;

        #pragma unroll
        for (int kt = 0; kt < 8; kt++) {
            #pragma unroll
            for (int nt = 0; nt < 8; nt++) {
                uint2 bb = *(const uint2*)&Kb[(nt * 8 + g) * 72 + kt * 8 + 2 * t];
                mma_tf32(sacc[0][nt], qf[0][kt], (const unsigned*)&bb);
                mma_tf32(sacc[1][nt], qf[1][kt], (const unsigned*)&bb);
            }
        }

        // ---- causal mask (only the last two k-tiles can cross the diagonal)
        if (kb >= 2 * qbi) {
            #pragma unroll
            for (int mt = 0; mt < 2; mt++)
                #pragma unroll
                for (int nt = 0; nt < 8; nt++) {
                    int c0 = kstart + nt * 8 + 2 * t;
                    int c1 = c0 + 1;
                    if (c0 > r0g[mt]) sacc[mt][nt][0] = -1e30f;
                    if (c1 > r0g[mt]) sacc[mt][nt][1] = -1e30f;
                    if (c0 > r1g[mt]) sacc[mt][nt][2] = -1e30f;
                    if (c1 > r1g[mt]) sacc[mt][nt][3] = -1e30f;
                }
        }

        // ---- online softmax (per M-tile) ----
        float nm0[2], nm1[2], alpha0[2], alpha1[2];
        #pragma unroll
        for (int mt = 0; mt < 2; mt++) {
            float mx0 = -1e30f, mx1 = -1e30f;
            #pragma unroll
            for (int nt = 0; nt < 8; nt++) {
                mx0 = fmaxf(mx0, fmaxf(sacc[mt][nt][0], sacc[mt][nt][1]));
                mx1 = fmaxf(mx1, fmaxf(sacc[mt][nt][2], sacc[mt][nt][3]));
            }
            mx0 = fmaxf(mx0, __shfl_xor_sync(0xffffffffu, mx0, 1));
            mx0 = fmaxf(mx0, __shfl_xor_sync(0xffffffffu, mx0, 2));
            mx1 = fmaxf(mx1, __shfl_xor_sync(0xffffffffu, mx1, 1));
            mx1 = fmaxf(mx1, __shfl_xor_sync(0xffffffffu, mx1, 2));
            nm0[mt] = fmaxf(m0[mt], mx0);
            nm1[mt] = fmaxf(m1[mt], mx1);
            alpha0[mt] = ex2f(m0[mt] - nm0[mt]);
            alpha1[mt] = ex2f(m1[mt] - nm1[mt]);
            m0[mt] = nm0[mt]; m1[mt] = nm1[mt];
            #pragma unroll
            for (int nt = 0; nt < 8; nt++) {
                oacc[mt][nt][0] *= alpha0[mt];
                oacc[mt][nt][1] *= alpha0[mt];
                oacc[mt][nt][2] *= alpha1[mt];
                oacc[mt][nt][3] *= alpha1[mt];
            }
        }

        // ---- fused exp + relayout + PV per kt (V B-frag reused 2x) ----
        float rs0[2] = {0.f, 0.f}, rs1[2] = {0.f, 0.f};
        #pragma unroll
        for (int kt = 0; kt < 8; kt++) {
            unsigned a[2][4];
            #pragma unroll
            for (int mt = 0; mt < 2; mt++) {
                float p00 = ex2f(sacc[mt][kt][0] - nm0[mt]);
                float p01 = ex2f(sacc[mt][kt][1] - nm0[mt]);
                float p10 = ex2f(sacc[mt][kt][2] - nm1[mt]);
                float p11 = ex2f(sacc[mt][kt][3] - nm1[mt]);
                rs0[mt] += p00 + p01;
                rs1[mt] += p10 + p11;
                float q00 = f2tf_f(p00), q01 = f2tf_f(p01);
                float q10 = f2tf_f(p10), q11 = f2tf_f(p11);
                float v00 = __shfl_sync(0xffffffffu, q00, srcA);
                float v01 = __shfl_sync(0xffffffffu, q01, srcA);
                float v10 = __shfl_sync(0xffffffffu, q10, srcA);
                float v11 = __shfl_sync(0xffffffffu, q11, srcA);
                float w00 = __shfl_sync(0xffffffffu, q00, srcB);
                float w01 = __shfl_sync(0xffffffffu, q01, srcB);
                float w10 = __shfl_sync(0xffffffffu, q10, srcB);
                float w11 = __shfl_sync(0xffffffffu, q11, srcB);
                a[mt][0] = __float_as_uint(sel ? v01 : v00);
                a[mt][1] = __float_as_uint(sel ? v11 : v10);
                a[mt][2] = __float_as_uint(sel ? w01 : w00);
                a[mt][3] = __float_as_uint(sel ? w11 : w10);
            }
            #pragma unroll
            for (int nt = 0; nt < 8; nt++) {
                uint2 bb = *(const uint2*)&Vb[(nt * 8 + g) * 72 + kt * 8 + 2 * t];
                mma_tf32(oacc[0][nt], a[0], (const unsigned*)&bb);
                mma_tf32(oacc[1][nt], a[1], (const unsigned*)&bb);
            }
        }
        #pragma unroll
        for (int mt = 0; mt < 2; mt++) {
            rs0[mt] += __shfl_xor_sync(0xffffffffu, rs0[mt], 1);
            rs0[mt] += __shfl_xor_sync(0xffffffffu, rs0[mt], 2);
            rs1[mt] += __shfl_xor_sync(0xffffffffu, rs1[mt], 1);
            rs1[mt] += __shfl_xor_sync(0xffffffffu, rs1[mt], 2);
            l0[mt] = l0[mt] * alpha0[mt] + rs0[mt];
            l1[mt] = l1[mt] * alpha1[mt] + rs1[mt];
        }

        __syncthreads();
    }

    // ---- epilogue ----
    #pragma unroll
    for (int mt = 0; mt < 2; mt++) {
        float inv0 = 1.f / l0[mt], inv1 = 1.f / l1[mt];
        #pragma unroll
        for (int nt = 0; nt < 8; nt++) {
            int col = h * HD + nt * 8 + 2 * t;
            *(float2*)&O[(size_t)r0g[mt] * DIM + col] =
                make_float2(oacc[mt][nt][0] * inv0, oacc[mt][nt][1] * inv0);
            *(float2*)&O[(size_t)r1g[mt] * DIM + col] =
                make_float2(oacc[mt][nt][2] * inv1, oacc[mt][nt][3] * inv1);
        }
    }
}

// ---------------------------------------------------------------------------
extern "C" void kernel_launch(void* const* d_in, const int* in_sizes, int n_in,
                              void* d_out, int out_size)
{
    const float* x   = (const float*)d_in[0];
    // d_in[1] = mask (causal) — analytic
    const float* q_w = (const float*)d_in[2];
    const float* q_b = (const float*)d_in[3];
    const float* k_w = (const float*)d_in[4];
    const float* k_b = (const float*)d_in[5];
    const float* v_w = (const float*)d_in[6];
    const float* v_b = (const float*)d_in[7];
    const float* o_w = (const float*)d_in[8];
    const float* o_b = (const float*)d_in[9];

    float* out  = (float*)d_out;
    float* kout = out + (size_t)T_SEQ * DIM;
    float* vout = kout + (size_t)KV_HEADS * T_SEQ * HD;

    float *qtbuf = nullptr, *abuf = nullptr, *ktbuf = nullptr, *vtbuf = nullptr;
    cudaGetSymbolAddress((void**)&qtbuf, g_Qt);
    cudaGetSymbolAddress((void**)&abuf,  g_att);
    cudaGetSymbolAddress((void**)&ktbuf, g_Kt);
    cudaGetSymbolAddress((void**)&vtbuf, g_Vt);

    const int gemm_smem  = (int)sizeof(GemmSmem);                 // 81920
    const int flash_smem = 2 * 2 * 64 * 72 * (int)sizeof(float);  // 73728
    cudaFuncSetAttribute(gemm_qkv, cudaFuncAttributeMaxDynamicSharedMemorySize, gemm_smem);
    cudaFuncSetAttribute(gemm_o,   cudaFuncAttributeMaxDynamicSharedMemorySize, gemm_smem);
    cudaFuncSetAttribute(flash_tf32, cudaFuncAttributeMaxDynamicSharedMemorySize, flash_smem);

    // fused Q/K/V projections (fills the chip: 384 CTAs)
    gemm_qkv<<<dim3(12, 32), 256, gemm_smem>>>(x, q_w, q_b, k_w, k_b, v_w, v_b,
                                               qtbuf, kout, ktbuf, vout, vtbuf);
    // causal attention -> g_att  (Br=128: 32 q-blocks x 16 heads)
    flash_tf32<<<dim3(T_SEQ / 128, HEADS), 128, flash_smem>>>(qtbuf, ktbuf,
                                                              vtbuf, abuf);
    // output projection -> out
    gemm_o<<<dim3(8, 32), 256, gemm_smem>>>(abuf, o_w, o_b, out);
}